// round 6
// baseline (speedup 1.0000x reference)
#include <cuda_runtime.h>
#include <math.h>

#define MAXN 80000
#define K 512
#define HITS_C 128

// ---------------- scratch (device globals; zero-initialized at load,
// re-zeroed at the end of kE so every kernel_launch sees zeros) ----------------
__device__ float g_q[MAXN];
__device__ float g_cnt[K], g_rep[K];
__device__ float2 g_ar[K];       // x = attraction sum, y = repulsion member-correction
__device__ float2 g_nd[K];       // x = payload num, y = payload den
__device__ unsigned long long g_packed[K];
__device__ float g_ax[K], g_ay[K], g_qa[K], g_ba[K];
__device__ float g_ccsum, g_nbeta, g_ncnt;

__device__ __forceinline__ float sqrt_approx(float x) {
    float r;
    asm("sqrt.approx.f32 %0, %1;" : "=f"(r) : "f"(x));
    return r;
}
__device__ __forceinline__ unsigned long long f32x2_add(unsigned long long a, unsigned long long b) {
    unsigned long long r;
    asm("add.rn.f32x2 %0, %1, %2;" : "=l"(r) : "l"(a), "l"(b));
    return r;
}
__device__ __forceinline__ unsigned long long f32x2_fma(unsigned long long a, unsigned long long b, unsigned long long c) {
    unsigned long long r;
    asm("fma.rn.f32x2 %0, %1, %2, %3;" : "=l"(r) : "l"(a), "l"(b), "l"(c));
    return r;
}
__device__ __forceinline__ unsigned long long pack2(float lo, float hi) {
    unsigned long long r;
    asm("mov.b64 %0, {%1, %2};" : "=l"(r) : "f"(lo), "f"(hi));
    return r;
}
__device__ __forceinline__ float lo32(unsigned long long v) {
    float a, b;
    asm("mov.b64 {%0, %1}, %2;" : "=f"(a), "=f"(b) : "l"(v));
    return a;
}
__device__ __forceinline__ float hi32(unsigned long long v) {
    float a, b;
    asm("mov.b64 {%0, %1}, %2;" : "=f"(a), "=f"(b) : "l"(v));
    return b;
}

// ---------------- per-hit pass (slim): q, argmax-beta, count, noise, cc ----------------
__global__ __launch_bounds__(256) void kA(
    const float* __restrict__ beta, const float2* __restrict__ cc,
    const int* __restrict__ tidx, int n)
{
    int i = blockIdx.x * blockDim.x + threadIdx.x;
    float cc2 = 0.f, nb = 0.f, nc = 0.f;
    if (i < n) {
        float b = fminf(fmaxf(beta[i], 1e-6f), 1.f - 1e-6f);
        // atanh(b) = 0.5*ln((1+b)/(1-b)) — fast MUFU path
        float at = 0.5f * __logf(__fdividef(1.f + b, 1.f - b));
        float q = fmaf(at, at, 0.1f);
        g_q[i] = q;
        float2 c = cc[i];
        cc2 = fmaf(c.x, c.x, c.y * c.y);
        int k = tidx[i];
        if (k >= 0) {
            atomicAdd(&g_cnt[k], 1.f);
            unsigned long long key =
                ((unsigned long long)__float_as_uint(b) << 32) |
                (unsigned int)(0x7FFFFFFF - i);  // ties -> smallest index (argmax semantics)
            atomicMax(&g_packed[k], key);
        } else {
            nb = b; nc = 1.f;
        }
    }
    #pragma unroll
    for (int off = 16; off > 0; off >>= 1) {
        cc2 += __shfl_down_sync(0xFFFFFFFFu, cc2, off);
        nb  += __shfl_down_sync(0xFFFFFFFFu, nb,  off);
        nc  += __shfl_down_sync(0xFFFFFFFFu, nc,  off);
    }
    __shared__ float w1[8], w2[8], w3[8];
    int lane = threadIdx.x & 31, wid = threadIdx.x >> 5;
    if (lane == 0) { w1[wid] = cc2; w2[wid] = nb; w3[wid] = nc; }
    __syncthreads();
    if (threadIdx.x == 0) {
        float s1 = 0.f, s2 = 0.f, s3 = 0.f;
        #pragma unroll
        for (int w = 0; w < 8; w++) { s1 += w1[w]; s2 += w2[w]; s3 += w3[w]; }
        atomicAdd(&g_ccsum, s1);
        atomicAdd(&g_nbeta, s2);
        atomicAdd(&g_ncnt,  s3);
    }
}

// ---------------- per-object: unpack alpha ----------------
__global__ void kB(const float2* __restrict__ cc) {
    int k = threadIdx.x;
    if (g_cnt[k] > 0.f) {
        unsigned long long p = g_packed[k];
        unsigned int bits = (unsigned int)(p >> 32);
        int idx = 0x7FFFFFFF - (int)(p & 0xFFFFFFFFull);
        float2 c = cc[idx];
        g_ax[k] = c.x; g_ay[k] = c.y;
        g_qa[k] = g_q[idx];
        g_ba[k] = __uint_as_float(bits);
    } else {
        g_ax[k] = 1e30f; g_ay[k] = 1e30f; g_qa[k] = 0.f; g_ba[k] = 1.f;
    }
}

// ---------------- hot loop: repulsion over ALL pairs (f32x2), fused with
// member-pair correction AND per-hit payload losses for this chunk ----------------
__global__ __launch_bounds__(512, 4) void kC(
    const float2* __restrict__ cc, const int* __restrict__ tidx,
    const float* __restrict__ beta,
    const float* __restrict__ pe, const float2* __restrict__ ppos,
    const float* __restrict__ pt, const float* __restrict__ pid,
    const float* __restrict__ te, const float2* __restrict__ tpos,
    const float* __restrict__ tt, int n)
{
    // shared: xy packed as {x0,x1,y0,y1} per 2 hits; q packed as {q0,q1}
    __shared__ __align__(16) float sxy[HITS_C * 2];
    __shared__ __align__(8)  float sq[HITS_C];
    int k = threadIdx.x;                   // object id (blockDim == K)
    int base = blockIdx.x * HITS_C;
    int gi = base + k;

    float hx = 0.f, hy = 0.f, hq = 0.f;
    int myk = -1;
    if (k < HITS_C) {
        float x = 1e30f, y = 1e30f, qv = 0.f;
        if (gi < n) {
            float2 c = cc[gi];
            x = c.x; y = c.y; qv = g_q[gi];
            myk = tidx[gi];
            hx = x; hy = y; hq = qv;
        }
        int p = k >> 1, l = k & 1;
        sxy[4 * p + l]     = x;
        sxy[4 * p + 2 + l] = y;
        sq[2 * p + l]      = qv;
    }
    float ax = g_ax[k], ay = g_ay[k];
    __syncthreads();

    unsigned long long nax = pack2(-ax, -ax);
    unsigned long long nay = pack2(-ay, -ay);
    unsigned long long eps2 = pack2(1e-6f, 1e-6f);
    const ulonglong2* xyp = (const ulonglong2*)sxy;
    const unsigned long long* qp = (const unsigned long long*)sq;

    float acc0 = 0.f, acc1 = 0.f;
    #pragma unroll 8
    for (int h = 0; h < HITS_C / 2; ++h) {
        ulonglong2 xy = xyp[h];             // LDS.128: {x0,x1},{y0,y1}
        unsigned long long dx = f32x2_add(xy.x, nax);
        unsigned long long dy = f32x2_add(xy.y, nay);
        unsigned long long d2 = f32x2_fma(dx, dx, eps2);
        d2 = f32x2_fma(dy, dy, d2);
        float s0 = sqrt_approx(lo32(d2));
        float s1 = sqrt_approx(hi32(d2));
        float t0 = __saturatef(1.f - s0);   // == relu(1-s), since 1-s <= 1
        float t1 = __saturatef(1.f - s1);
        unsigned long long q2 = qp[h];
        acc0 = fmaf(t0, lo32(q2), acc0);
        acc1 = fmaf(t1, hi32(q2), acc1);
    }
    atomicAdd(&g_rep[k], acc0 + acc1);

    if (myk >= 0) {
        // ---- member-pair correction (bit-exact with loop math) ----
        float axk = g_ax[myk], ayk = g_ay[myk];
        float dx = hx - axk, dy = hy - ayk;
        float d2e = fmaf(dx, dx, 1e-6f);
        d2e = fmaf(dy, dy, d2e);
        float s = sqrt_approx(d2e);
        float t = __saturatef(1.f - s);
        float d2raw = fmaf(dx, dx, dy * dy);
        atomicAdd(&g_ar[myk], make_float2(d2raw * hq, -t * hq));

        // ---- payload losses for this hit ----
        float b = fminf(fmaxf(beta[gi], 1e-6f), 1.f - 1e-6f);
        float tener = te[gi];
        float ediff = fabsf(tener - pe[gi]);
        float el = fmaf(0.01f, ediff, 10.f * __expf(-0.1f * ediff * ediff));
        float xl = el * 0.1f;
        xl = (xl > 1.f) ? __logf(xl + 1.f) : xl;
        el = xl * 10.f;
        float2 tp = tpos[gi], pp = ppos[gi];
        float dpx = tp.x - pp.x, dpy = tp.y - pp.y;
        float pd2 = fmaf(dpx, dpx, dpy * dpy);
        float xr = sqrtf(fmaf(pd2, 0.01f, 0.01f));
        float plh = (xr < 10.f) ? xr * xr : fmaf(20.f, xr - 10.f, 100.f);
        float xp = plh * (1.f / 3.f);
        xp = (xp > 1.f) ? __logf(xp + 1.f) : xp;
        float pl = xp * 3.f;
        float dt = tt[gi] - pt[gi];
        float adt = fabsf(dt);
        float th = (adt < 2.f) ? dt * dt : fmaf(4.f, adt - 2.f, 4.f);
        float xt = th * (1.f / 6.f);
        xt = (xt > 1.f) ? __logf(xt + 1.f) : xt;
        th = xt * 6.f;
        float sid = 0.f;
        #pragma unroll
        for (int j = 0; j < 6; j++) { float v = pid[gi * 6 + j]; sid = fmaf(v, v, sid); }
        float clf = 1e-8f * (sid * (1.f / 6.f));

        float payload = el + pl + th + clf;
        float ew = (tener > 10.f) ? 1.f : fmaxf((tener - 0.5f) * (1.f / 9.5f), 0.f);
        float pw = b * ew;
        atomicAdd(&g_nd[myk], make_float2(payload * pw, pw));
    }
}

// ---------------- finalize + re-zero scratch for the next call ----------------
__global__ void kE(float* __restrict__ out, int n) {
    int k = threadIdx.x;
    float s1 = 0.f, ho = 0.f;
    float cnt = g_cnt[k];
    if (cnt > 0.f) {
        ho = 1.f;
        float qa = g_qa[k];
        float2 ar = g_ar[k];
        float a  = qa * ar.x / (cnt + 1e-9f);
        float r  = qa * (g_rep[k] + ar.y) / ((float)n - cnt + 1e-9f);
        float bl = 1.f - g_ba[k];
        float2 nd = g_nd[k];
        float pl = nd.x / (nd.y + 1e-9f);
        s1 = a + r + bl + pl;
    }
    __shared__ float sh1[K], sh2[K];
    sh1[k] = s1; sh2[k] = ho;
    __syncthreads();
    for (int off = K / 2; off > 0; off >>= 1) {
        if (k < off) { sh1[k] += sh1[k + off]; sh2[k] += sh2[k + off]; }
        __syncthreads();
    }
    if (k == 0) {
        float nobj = sh2[0] + 1e-9f;
        float total = sh1[0] / nobj;
        total += g_nbeta / (g_ncnt + 1e-9f);
        total += 0.001f * g_ccsum / ((float)n * 2.f);
        out[0] = total;
    }
    // re-zero all accumulators so the next kernel_launch starts clean
    g_cnt[k] = 0.f; g_rep[k] = 0.f;
    g_ar[k] = make_float2(0.f, 0.f);
    g_nd[k] = make_float2(0.f, 0.f);
    g_packed[k] = 0ull;
    if (k == 0) { g_ccsum = 0.f; g_nbeta = 0.f; g_ncnt = 0.f; }
}

extern "C" void kernel_launch(void* const* d_in, const int* in_sizes, int n_in,
                              void* d_out, int out_size) {
    const float*  beta = (const float*)d_in[0];
    const float2* cc   = (const float2*)d_in[1];
    const float*  pe   = (const float*)d_in[2];
    const float2* ppos = (const float2*)d_in[3];
    const float*  pt   = (const float*)d_in[4];
    const float*  pid  = (const float*)d_in[5];
    const int*    tidx = (const int*)d_in[6];
    const float*  te   = (const float*)d_in[7];
    const float2* tpos = (const float2*)d_in[8];
    const float*  tt   = (const float*)d_in[9];
    int n = in_sizes[0];
    if (n > MAXN) n = MAXN;

    kA<<<(n + 255) / 256, 256>>>(beta, cc, tidx, n);
    kB<<<1, K>>>(cc);
    int gc = (n + HITS_C - 1) / HITS_C;
    kC<<<gc, K>>>(cc, tidx, beta, pe, ppos, pt, pid, te, tpos, tt, n);
    kE<<<1, K>>>((float*)d_out, n);
}

// round 7
// speedup vs baseline: 1.1306x; 1.1306x over previous
#include <cuda_runtime.h>
#include <math.h>

#define MAXN 80000
#define K 512
#define HITS_C 128

// ---------------- scratch (device globals; zero-initialized at load,
// re-zeroed by the finalizing block so every kernel_launch sees zeros) --------
__device__ float g_q[MAXN];
__device__ float g_cnt[K], g_rep[K];
__device__ float2 g_ar[K];       // x = attraction sum, y = repulsion member-correction
__device__ float2 g_nd[K];       // x = payload num, y = payload den
__device__ unsigned long long g_packed[K];
__device__ float g_ccsum, g_nbeta, g_ncnt;
__device__ unsigned int g_done;

__device__ __forceinline__ float sqrt_approx(float x) {
    float r;
    asm("sqrt.approx.f32 %0, %1;" : "=f"(r) : "f"(x));
    return r;
}
__device__ __forceinline__ unsigned long long f32x2_add(unsigned long long a, unsigned long long b) {
    unsigned long long r;
    asm("add.rn.f32x2 %0, %1, %2;" : "=l"(r) : "l"(a), "l"(b));
    return r;
}
__device__ __forceinline__ unsigned long long f32x2_fma(unsigned long long a, unsigned long long b, unsigned long long c) {
    unsigned long long r;
    asm("fma.rn.f32x2 %0, %1, %2, %3;" : "=l"(r) : "l"(a), "l"(b), "l"(c));
    return r;
}
__device__ __forceinline__ unsigned long long pack2(float lo, float hi) {
    unsigned long long r;
    asm("mov.b64 %0, {%1, %2};" : "=l"(r) : "f"(lo), "f"(hi));
    return r;
}
__device__ __forceinline__ float lo32(unsigned long long v) {
    float a, b;
    asm("mov.b64 {%0, %1}, %2;" : "=f"(a), "=f"(b) : "l"(v));
    return a;
}
__device__ __forceinline__ float hi32(unsigned long long v) {
    float a, b;
    asm("mov.b64 {%0, %1}, %2;" : "=f"(a), "=f"(b) : "l"(v));
    return b;
}

// ---------------- per-hit pass: q, argmax-beta, count, noise, cc ----------------
__global__ __launch_bounds__(256) void kA(
    const float* __restrict__ beta, const float2* __restrict__ cc,
    const int* __restrict__ tidx, int n)
{
    int i = blockIdx.x * blockDim.x + threadIdx.x;
    float cc2 = 0.f, nb = 0.f, nc = 0.f;
    if (i < n) {
        float b = fminf(fmaxf(beta[i], 1e-6f), 1.f - 1e-6f);
        // atanh(b) = 0.5*ln((1+b)/(1-b)) — fast MUFU path
        float at = 0.5f * __logf(__fdividef(1.f + b, 1.f - b));
        float q = fmaf(at, at, 0.1f);
        g_q[i] = q;
        float2 c = cc[i];
        cc2 = fmaf(c.x, c.x, c.y * c.y);
        int k = tidx[i];
        if (k >= 0) {
            atomicAdd(&g_cnt[k], 1.f);
            unsigned long long key =
                ((unsigned long long)__float_as_uint(b) << 32) |
                (unsigned int)(0x7FFFFFFF - i);  // ties -> smallest index (argmax semantics)
            atomicMax(&g_packed[k], key);
        } else {
            nb = b; nc = 1.f;
        }
    }
    #pragma unroll
    for (int off = 16; off > 0; off >>= 1) {
        cc2 += __shfl_down_sync(0xFFFFFFFFu, cc2, off);
        nb  += __shfl_down_sync(0xFFFFFFFFu, nb,  off);
        nc  += __shfl_down_sync(0xFFFFFFFFu, nc,  off);
    }
    __shared__ float w1[8], w2[8], w3[8];
    int lane = threadIdx.x & 31, wid = threadIdx.x >> 5;
    if (lane == 0) { w1[wid] = cc2; w2[wid] = nb; w3[wid] = nc; }
    __syncthreads();
    if (threadIdx.x == 0) {
        float s1 = 0.f, s2 = 0.f, s3 = 0.f;
        #pragma unroll
        for (int w = 0; w < 8; w++) { s1 += w1[w]; s2 += w2[w]; s3 += w3[w]; }
        atomicAdd(&g_ccsum, s1);
        atomicAdd(&g_nbeta, s2);
        atomicAdd(&g_ncnt,  s3);
    }
}

// ---------------- hot kernel: inline alpha table + all-pairs repulsion (f32x2)
// + member correction + payload + fenced last-block finalize ----------------
__global__ __launch_bounds__(512, 4) void kC(
    const float2* __restrict__ cc, const int* __restrict__ tidx,
    const float* __restrict__ beta,
    const float* __restrict__ pe, const float2* __restrict__ ppos,
    const float* __restrict__ pt, const float* __restrict__ pid,
    const float* __restrict__ te, const float2* __restrict__ tpos,
    const float* __restrict__ tt,
    float* __restrict__ out, int n, int nblocks)
{
    __shared__ __align__(16) float sxy[HITS_C * 2];  // {x0,x1,y0,y1} per 2 hits
    __shared__ __align__(8)  float sq[HITS_C];       // {q0,q1}
    __shared__ float s_ax[K], s_ay[K];
    int k = threadIdx.x;                   // object id (blockDim == K)
    int base = blockIdx.x * HITS_C;
    int gi = base + k;

    // ---- inline alpha table (kB's work, per block; all L2-hot) ----
    {
        float ax = 1e30f, ay = 1e30f;
        if (g_cnt[k] > 0.f) {
            unsigned long long p = g_packed[k];
            int idx = 0x7FFFFFFF - (int)(p & 0xFFFFFFFFull);
            float2 c = cc[idx];
            ax = c.x; ay = c.y;
        }
        s_ax[k] = ax; s_ay[k] = ay;
    }

    float hx = 0.f, hy = 0.f, hq = 0.f;
    int myk = -1;
    if (k < HITS_C) {
        float x = 1e30f, y = 1e30f, qv = 0.f;
        if (gi < n) {
            float2 c = cc[gi];
            x = c.x; y = c.y; qv = g_q[gi];
            myk = tidx[gi];
            hx = x; hy = y; hq = qv;
        }
        int p = k >> 1, l = k & 1;
        sxy[4 * p + l]     = x;
        sxy[4 * p + 2 + l] = y;
        sq[2 * p + l]      = qv;
    }
    __syncthreads();
    float ax = s_ax[k], ay = s_ay[k];

    unsigned long long nax = pack2(-ax, -ax);
    unsigned long long nay = pack2(-ay, -ay);
    unsigned long long eps2 = pack2(1e-6f, 1e-6f);
    const ulonglong2* xyp = (const ulonglong2*)sxy;
    const unsigned long long* qp = (const unsigned long long*)sq;

    float acc0 = 0.f, acc1 = 0.f;
    #pragma unroll 8
    for (int h = 0; h < HITS_C / 2; ++h) {
        ulonglong2 xy = xyp[h];             // LDS.128: {x0,x1},{y0,y1}
        unsigned long long dx = f32x2_add(xy.x, nax);
        unsigned long long dy = f32x2_add(xy.y, nay);
        unsigned long long d2 = f32x2_fma(dx, dx, eps2);
        d2 = f32x2_fma(dy, dy, d2);
        float s0 = sqrt_approx(lo32(d2));
        float s1 = sqrt_approx(hi32(d2));
        float t0 = __saturatef(1.f - s0);   // == relu(1-s), since 1-s <= 1
        float t1 = __saturatef(1.f - s1);
        unsigned long long q2 = qp[h];
        acc0 = fmaf(t0, lo32(q2), acc0);
        acc1 = fmaf(t1, hi32(q2), acc1);
    }
    atomicAdd(&g_rep[k], acc0 + acc1);

    if (myk >= 0) {
        // ---- member-pair correction (bit-exact with loop math) ----
        float axk = s_ax[myk], ayk = s_ay[myk];
        float dx = hx - axk, dy = hy - ayk;
        float d2e = fmaf(dx, dx, 1e-6f);
        d2e = fmaf(dy, dy, d2e);
        float s = sqrt_approx(d2e);
        float t = __saturatef(1.f - s);
        float d2raw = fmaf(dx, dx, dy * dy);
        atomicAdd(&g_ar[myk], make_float2(d2raw * hq, -t * hq));

        // ---- payload losses for this hit ----
        float b = fminf(fmaxf(beta[gi], 1e-6f), 1.f - 1e-6f);
        float tener = te[gi];
        float ediff = fabsf(tener - pe[gi]);
        float el = fmaf(0.01f, ediff, 10.f * __expf(-0.1f * ediff * ediff));
        float xl = el * 0.1f;
        xl = (xl > 1.f) ? __logf(xl + 1.f) : xl;
        el = xl * 10.f;
        float2 tp = tpos[gi], pp = ppos[gi];
        float dpx = tp.x - pp.x, dpy = tp.y - pp.y;
        float pd2 = fmaf(dpx, dpx, dpy * dpy);
        float xr = sqrtf(fmaf(pd2, 0.01f, 0.01f));
        float plh = (xr < 10.f) ? xr * xr : fmaf(20.f, xr - 10.f, 100.f);
        float xp = plh * (1.f / 3.f);
        xp = (xp > 1.f) ? __logf(xp + 1.f) : xp;
        float pl = xp * 3.f;
        float dt = tt[gi] - pt[gi];
        float adt = fabsf(dt);
        float th = (adt < 2.f) ? dt * dt : fmaf(4.f, adt - 2.f, 4.f);
        float xt = th * (1.f / 6.f);
        xt = (xt > 1.f) ? __logf(xt + 1.f) : xt;
        th = xt * 6.f;
        float sid = 0.f;
        #pragma unroll
        for (int j = 0; j < 6; j++) { float v = pid[gi * 6 + j]; sid = fmaf(v, v, sid); }
        float clf = 1e-8f * (sid * (1.f / 6.f));

        float payload = el + pl + th + clf;
        float ew = (tener > 10.f) ? 1.f : fmaxf((tener - 0.5f) * (1.f / 9.5f), 0.f);
        float pw = b * ew;
        atomicAdd(&g_nd[myk], make_float2(payload * pw, pw));
    }

    // ---- fenced last-block finalize ----
    __shared__ unsigned int s_ticket;
    __threadfence();
    __syncthreads();
    if (k == 0) s_ticket = atomicAdd(&g_done, 1u);
    __syncthreads();
    if (s_ticket != (unsigned int)(nblocks - 1)) return;

    // this is the last block: all atomics from all blocks are visible
    float s1 = 0.f, ho = 0.f;
    float cnt = g_cnt[k];
    if (cnt > 0.f) {
        ho = 1.f;
        unsigned long long p = g_packed[k];
        int idx = 0x7FFFFFFF - (int)(p & 0xFFFFFFFFull);
        float ba = __uint_as_float((unsigned int)(p >> 32));
        float qa = g_q[idx];
        float2 ar = g_ar[k];
        float a  = qa * ar.x / (cnt + 1e-9f);
        float r  = qa * (g_rep[k] + ar.y) / ((float)n - cnt + 1e-9f);
        float bl = 1.f - ba;
        float2 nd = g_nd[k];
        float pl = nd.x / (nd.y + 1e-9f);
        s1 = a + r + bl + pl;
    }
    // shuffle-based reduction over 512 threads
    #pragma unroll
    for (int off = 16; off > 0; off >>= 1) {
        s1 += __shfl_down_sync(0xFFFFFFFFu, s1, off);
        ho += __shfl_down_sync(0xFFFFFFFFu, ho, off);
    }
    __shared__ float r1[16], r2[16];
    int lane = k & 31, wid = k >> 5;
    if (lane == 0) { r1[wid] = s1; r2[wid] = ho; }
    __syncthreads();
    if (k == 0) {
        float t1 = 0.f, t2 = 0.f;
        #pragma unroll
        for (int w = 0; w < 16; w++) { t1 += r1[w]; t2 += r2[w]; }
        float total = t1 / (t2 + 1e-9f);
        total += g_nbeta / (g_ncnt + 1e-9f);
        total += 0.001f * g_ccsum / ((float)n * 2.f);
        out[0] = total;
    }
    // re-zero all accumulators for the next call
    g_cnt[k] = 0.f; g_rep[k] = 0.f;
    g_ar[k] = make_float2(0.f, 0.f);
    g_nd[k] = make_float2(0.f, 0.f);
    g_packed[k] = 0ull;
    if (k == 0) { g_ccsum = 0.f; g_nbeta = 0.f; g_ncnt = 0.f; g_done = 0u; }
}

extern "C" void kernel_launch(void* const* d_in, const int* in_sizes, int n_in,
                              void* d_out, int out_size) {
    const float*  beta = (const float*)d_in[0];
    const float2* cc   = (const float2*)d_in[1];
    const float*  pe   = (const float*)d_in[2];
    const float2* ppos = (const float2*)d_in[3];
    const float*  pt   = (const float*)d_in[4];
    const float*  pid  = (const float*)d_in[5];
    const int*    tidx = (const int*)d_in[6];
    const float*  te   = (const float*)d_in[7];
    const float2* tpos = (const float2*)d_in[8];
    const float*  tt   = (const float*)d_in[9];
    int n = in_sizes[0];
    if (n > MAXN) n = MAXN;

    kA<<<(n + 255) / 256, 256>>>(beta, cc, tidx, n);
    int gc = (n + HITS_C - 1) / HITS_C;
    kC<<<gc, K>>>(cc, tidx, beta, pe, ppos, pt, pid, te, tpos, tt,
                  (float*)d_out, n, gc);
}